// round 15
// baseline (speedup 1.0000x reference)
#include <cuda_runtime.h>
#include <cuda_bf16.h>
#include <math.h>
#include <cstdint>

#define NTOK 4096
#define NEXP 8
#define CDIM 768
#define HID  3072
#define TM   128
#define PADN (NTOK + NEXP * TM)   // 5120
#define MTILES (PADN / TM)        // 40

#define APITCH 144                // 32 floats + 16B pad; A and B rows
#define SB_OFF 18432              // A tile 128*144
#define SSZ    36864              // stage: A 18432 + B 18432
#define SMEM_SZ (3 * SSZ)         // 110592; >= 67584 epilogue staging

// ---------------- scratch ----------------
__device__ int g_perm[PADN];
__device__ int g_tile_expert[MTILES];
__device__ __align__(128) float g_xr[(size_t)PADN * CDIM];
__device__ __align__(128) float g_h[(size_t)PADN * HID];
__device__ __align__(128) float g_wgT[(size_t)NEXP * HID * CDIM];  // [e][n][k]
__device__ __align__(128) float g_wiT[(size_t)NEXP * HID * CDIM];  // [e][n][k]
__device__ __align__(128) float g_woT[(size_t)NEXP * CDIM * HID];  // [e][n][k]

// ---------------- helpers ----------------
static __device__ __forceinline__ uint32_t smem_u32(const void* p) {
    uint32_t a;
    asm("{ .reg .u64 t; cvta.to.shared.u64 t, %1; cvt.u32.u64 %0, t; }" : "=r"(a) : "l"(p));
    return a;
}
static __device__ __forceinline__ float tf32r(float x) {
    uint32_t u;
    asm("cvt.rna.tf32.f32 %0, %1;" : "=r"(u) : "f"(x));
    return __uint_as_float(u);
}
static __device__ __forceinline__ void ldsm4(uint32_t* r, uint32_t a) {
    asm volatile("ldmatrix.sync.aligned.m8n8.x4.shared.b16 {%0,%1,%2,%3}, [%4];"
        : "=r"(r[0]), "=r"(r[1]), "=r"(r[2]), "=r"(r[3]) : "r"(a));
}
static __device__ __forceinline__ void mma_tf32(float* c, const uint32_t* a,
                                                uint32_t b0, uint32_t b1) {
    asm volatile("mma.sync.aligned.m16n8k8.row.col.f32.tf32.tf32.f32 "
        "{%0,%1,%2,%3}, {%4,%5,%6,%7}, {%8,%9}, {%0,%1,%2,%3};"
        : "+f"(c[0]), "+f"(c[1]), "+f"(c[2]), "+f"(c[3])
        : "r"(a[0]), "r"(a[1]), "r"(a[2]), "r"(a[3]), "r"(b0), "r"(b1));
}
static __device__ __forceinline__ void cpa16(uint32_t d, const float* s) {
    asm volatile("cp.async.cg.shared.global [%0], [%1], 16;"
        :: "r"(d), "l"(s) : "memory");
}
#define CPA_COMMIT() asm volatile("cp.async.commit_group;" ::: "memory")
#define CPA_WAIT1()  asm volatile("cp.async.wait_group 1;" ::: "memory")

// ---------------------------------------------------------------------------
// route
// ---------------------------------------------------------------------------
__global__ void route_kernel(const int* __restrict__ mapped) {
    __shared__ int cnt[NEXP];
    __shared__ int off[NEXP];
    __shared__ int fill[NEXP];
    int tid = threadIdx.x;
    if (tid < NEXP) { cnt[tid] = 0; fill[tid] = 0; }
    __syncthreads();
    for (int i = tid; i < NTOK; i += blockDim.x) atomicAdd(&cnt[mapped[i]], 1);
    __syncthreads();
    if (tid == 0) {
        int o = 0;
        for (int e = 0; e < NEXP; e++) {
            off[e] = o;
            int tiles = (cnt[e] + TM - 1) / TM;
            for (int t = 0; t < tiles; t++) g_tile_expert[o / TM + t] = e;
            o += tiles * TM;
        }
        for (int t = o / TM; t < MTILES; t++) g_tile_expert[t] = -1;
    }
    __syncthreads();
    for (int i = tid; i < PADN; i += blockDim.x) g_perm[i] = -1;
    __syncthreads();
    for (int i = tid; i < NTOK; i += blockDim.x) {
        int e = mapped[i];
        g_perm[off[e] + atomicAdd(&fill[e], 1)] = i;
    }
}

// ---------------------------------------------------------------------------
// prep_x: gather-permute x rows + round to tf32 (pad rows -> 0)
// ---------------------------------------------------------------------------
__global__ __launch_bounds__(256) void prep_x_kernel(const float* __restrict__ x) {
    int row = blockIdx.x, tid = threadIdx.x;
    int prow = g_perm[row];
    const float* xr = (prow >= 0) ? x + (size_t)prow * CDIM : nullptr;
    #pragma unroll
    for (int j = 0; j < 3; j++) {
        int i = tid + 256 * j;
        float v = xr ? xr[i] : 0.0f;
        g_xr[(size_t)row * CDIM + i] = tf32r(v);
    }
}

// ---------------------------------------------------------------------------
// prep_wT: transpose [K][N] -> [N][K] per expert with tf32 rna rounding.
// dst selected DEVICE-SIDE via `which` (host cannot pass __device__ symbols).
// ---------------------------------------------------------------------------
__global__ __launch_bounds__(256) void prep_wT_kernel(
    const float* __restrict__ Wg, const float* __restrict__ Wi,
    const float* __restrict__ Wo, int which)
{
    __shared__ float ts[64][65];
    const float* src = (which == 0) ? Wg : (which == 1) ? Wi : Wo;
    float* dst = (which == 0) ? g_wgT : (which == 1) ? g_wiT : g_woT;
    int K = (which == 2) ? HID : CDIM;
    int N = (which == 2) ? CDIM : HID;

    int e = blockIdx.z;
    int n0 = blockIdx.x * 64, k0 = blockIdx.y * 64;
    const float* se = src + (size_t)e * K * N;
    float* de = dst + (size_t)e * N * K;
    int tid = threadIdx.x;
    int r = tid >> 4, c4 = tid & 15;
    #pragma unroll
    for (int i = 0; i < 4; i++) {
        int row = r + 16 * i;
        float4 v = *(const float4*)(se + (size_t)(k0 + row) * N + n0 + c4 * 4);
        ts[row][c4 * 4 + 0] = tf32r(v.x);
        ts[row][c4 * 4 + 1] = tf32r(v.y);
        ts[row][c4 * 4 + 2] = tf32r(v.z);
        ts[row][c4 * 4 + 3] = tf32r(v.w);
    }
    __syncthreads();
    #pragma unroll
    for (int i = 0; i < 4; i++) {
        int n = r + 16 * i;
        float4 o;
        o.x = ts[c4 * 4 + 0][n];
        o.y = ts[c4 * 4 + 1][n];
        o.z = ts[c4 * 4 + 2][n];
        o.w = ts[c4 * 4 + 3][n];
        *(float4*)(de + (size_t)(n0 + n) * K + k0 + c4 * 4) = o;
    }
}

// ---------------------------------------------------------------------------
// up GEMM: [128 tok] x [G 64 | I 64 cols], K=768.
// 3-stage cp.async pipeline; A ldsm + n-major conflict-free scalar B.
// ---------------------------------------------------------------------------
__global__ __launch_bounds__(256, 2) void up_gemm(
    const float* __restrict__ bg, const float* __restrict__ bi)
{
    extern __shared__ char smem[];
    int mtile = blockIdx.x;
    int e = g_tile_expert[mtile];
    if (e < 0) return;
    int gn0 = blockIdx.y * 64;
    int tid = threadIdx.x, lane = tid & 31, wid = tid >> 5;
    int wm = wid >> 2, wn = wid & 3;
    uint32_t sb = smem_u32(smem);

    const float* pA = g_xr + (size_t)(mtile * TM + (tid >> 1)) * CDIM + (tid & 1) * 16;
    uint32_t aoff = sb + (tid >> 1) * APITCH + (tid & 1) * 64;
    int brow = tid >> 1;
    const float* pB = ((brow < 64)
        ? g_wgT + ((size_t)e * HID + gn0 + brow) * CDIM
        : g_wiT + ((size_t)e * HID + gn0 + brow - 64) * CDIM) + (tid & 1) * 16;
    uint32_t boff = sb + SB_OFF + brow * APITCH + (tid & 1) * 64;

    // prologue: stages 0,1
    #pragma unroll
    for (int s = 0; s < 2; s++) {
        uint32_t so = s * SSZ;
        const float* ga = pA + s * 32;
        const float* gb = pB + s * 32;
        #pragma unroll
        for (int i = 0; i < 4; i++) {
            cpa16(aoff + so + i * 16, ga + i * 4);
            cpa16(boff + so + i * 16, gb + i * 4);
        }
        CPA_COMMIT();
    }

    float acc[4][4][4] = {};
    int l7 = lane & 7, lb8 = ((lane >> 3) & 1) * 8, lh = lane >> 4;
    int a_lane = (l7 + lb8) * APITCH + lh * 16;
    int bgrp = lane >> 2, bk = lane & 3;
    int b_base = SB_OFF + (wn * 32 + bgrp) * APITCH + bk * 4;

    for (int s = 0; s < 24; s++) {
        CPA_WAIT1();
        __syncthreads();
        if (s + 2 < 24) {
            uint32_t so = ((s + 2) % 3) * SSZ;
            const float* ga = pA + (s + 2) * 32;
            const float* gb = pB + (s + 2) * 32;
            #pragma unroll
            for (int i = 0; i < 4; i++) {
                cpa16(aoff + so + i * 16, ga + i * 4);
                cpa16(boff + so + i * 16, gb + i * 4);
            }
        }
        CPA_COMMIT();
        int cso = (s % 3) * SSZ;
        #pragma unroll
        for (int c = 0; c < 4; c++) {
            uint32_t a[4][4];
            #pragma unroll
            for (int mi = 0; mi < 4; mi++)
                ldsm4(a[mi], sb + cso + (wm * 64 + mi * 16) * APITCH + a_lane + c * 32);
            uint32_t b0[4], b1[4];
            int kb = cso + b_base + c * 32;
            #pragma unroll
            for (int nj = 0; nj < 4; nj++) {
                b0[nj] = *(const uint32_t*)(smem + kb + nj * 8 * APITCH);
                b1[nj] = *(const uint32_t*)(smem + kb + nj * 8 * APITCH + 16);
            }
            #pragma unroll
            for (int mi = 0; mi < 4; mi++)
                #pragma unroll
                for (int nj = 0; nj < 4; nj++)
                    mma_tf32(acc[mi][nj], a[mi], b0[nj], b1[nj]);
        }
    }
    __syncthreads();

    // epilogue: stage, pair G/I, SiLU, round to tf32, store h
    float* S = (float*)smem;
    int g = lane >> 2, tq = lane & 3;
    #pragma unroll
    for (int mi = 0; mi < 4; mi++) {
        int r0 = wm * 64 + mi * 16 + g;
        #pragma unroll
        for (int nj = 0; nj < 4; nj++) {
            int col = wn * 32 + nj * 8 + 2 * tq;
            S[r0 * 132 + col]           = acc[mi][nj][0];
            S[r0 * 132 + col + 1]       = acc[mi][nj][1];
            S[(r0 + 8) * 132 + col]     = acc[mi][nj][2];
            S[(r0 + 8) * 132 + col + 1] = acc[mi][nj][3];
        }
    }
    __syncthreads();
    {
        int row = tid >> 1, cb = (tid & 1) * 32;
        const float* bgp = bg + (size_t)e * HID + gn0;
        const float* bip = bi + (size_t)e * HID + gn0;
        float* hp = g_h + (size_t)(mtile * TM + row) * HID + gn0 + cb;
        #pragma unroll
        for (int j0 = 0; j0 < 32; j0 += 4) {
            float4 o;
            float* op = (float*)&o;
            #pragma unroll
            for (int q = 0; q < 4; q++) {
                int c = cb + j0 + q;
                float gv = S[row * 132 + c] + bgp[c];
                float iv = S[row * 132 + 64 + c] + bip[c];
                op[q] = tf32r((gv / (1.0f + __expf(-gv))) * iv);
            }
            *(float4*)(hp + j0) = o;
        }
    }
}

// ---------------------------------------------------------------------------
// down GEMM: y = h @ Wo + bo, K=3072, BN=128, 3-stage cp.async, scatter.
// ---------------------------------------------------------------------------
__global__ __launch_bounds__(256, 2) void down_gemm(
    const float* __restrict__ bo, float* __restrict__ out)
{
    extern __shared__ char smem[];
    int mtile = blockIdx.x;
    int e = g_tile_expert[mtile];
    if (e < 0) return;
    int gn0 = blockIdx.y * 128;
    int tid = threadIdx.x, lane = tid & 31, wid = tid >> 5;
    int wm = wid >> 2, wn = wid & 3;
    uint32_t sb = smem_u32(smem);

    const float* pA = g_h + (size_t)(mtile * TM + (tid >> 1)) * HID + (tid & 1) * 16;
    uint32_t aoff = sb + (tid >> 1) * APITCH + (tid & 1) * 64;
    int brow = tid >> 1;
    const float* pB = g_woT + ((size_t)e * CDIM + gn0 + brow) * HID + (tid & 1) * 16;
    uint32_t boff = sb + SB_OFF + brow * APITCH + (tid & 1) * 64;

    #pragma unroll
    for (int s = 0; s < 2; s++) {
        uint32_t so = s * SSZ;
        const float* ga = pA + s * 32;
        const float* gb = pB + s * 32;
        #pragma unroll
        for (int i = 0; i < 4; i++) {
            cpa16(aoff + so + i * 16, ga + i * 4);
            cpa16(boff + so + i * 16, gb + i * 4);
        }
        CPA_COMMIT();
    }

    float acc[4][4][4] = {};
    int l7 = lane & 7, lb8 = ((lane >> 3) & 1) * 8, lh = lane >> 4;
    int a_lane = (l7 + lb8) * APITCH + lh * 16;
    int bgrp = lane >> 2, bk = lane & 3;
    int b_base = SB_OFF + (wn * 32 + bgrp) * APITCH + bk * 4;

    for (int s = 0; s < 96; s++) {
        CPA_WAIT1();
        __syncthreads();
        if (s + 2 < 96) {
            uint32_t so = ((s + 2) % 3) * SSZ;
            const float* ga = pA + (s + 2) * 32;
            const float* gb = pB + (s + 2) * 32;
            #pragma unroll
            for (int i = 0; i < 4; i++) {
                cpa16(aoff + so + i * 16, ga + i * 4);
                cpa16(boff + so + i * 16, gb + i * 4);
            }
        }
        CPA_COMMIT();
        int cso = (s % 3) * SSZ;
        #pragma unroll
        for (int c = 0; c < 4; c++) {
            uint32_t a[4][4];
            #pragma unroll
            for (int mi = 0; mi < 4; mi++)
                ldsm4(a[mi], sb + cso + (wm * 64 + mi * 16) * APITCH + a_lane + c * 32);
            uint32_t b0[4], b1[4];
            int kb = cso + b_base + c * 32;
            #pragma unroll
            for (int nj = 0; nj < 4; nj++) {
                b0[nj] = *(const uint32_t*)(smem + kb + nj * 8 * APITCH);
                b1[nj] = *(const uint32_t*)(smem + kb + nj * 8 * APITCH + 16);
            }
            #pragma unroll
            for (int mi = 0; mi < 4; mi++)
                #pragma unroll
                for (int nj = 0; nj < 4; nj++)
                    mma_tf32(acc[mi][nj], a[mi], b0[nj], b1[nj]);
        }
    }

    // epilogue: bias + scatter directly from regs
    int g = lane >> 2, tq = lane & 3;
    const float* bop = bo + (size_t)e * CDIM;
    #pragma unroll
    for (int mi = 0; mi < 4; mi++) {
        int r0 = wm * 64 + mi * 16 + g;
        int p0 = g_perm[mtile * TM + r0];
        int p1 = g_perm[mtile * TM + r0 + 8];
        #pragma unroll
        for (int nj = 0; nj < 4; nj++) {
            int col = gn0 + wn * 32 + nj * 8 + 2 * tq;
            float2 b = *(const float2*)(bop + col);
            if (p0 >= 0)
                *(float2*)&out[(size_t)p0 * CDIM + col] =
                    make_float2(acc[mi][nj][0] + b.x, acc[mi][nj][1] + b.y);
            if (p1 >= 0)
                *(float2*)&out[(size_t)p1 * CDIM + col] =
                    make_float2(acc[mi][nj][2] + b.x, acc[mi][nj][3] + b.y);
        }
    }
}

// ---------------------------------------------------------------------------
extern "C" void kernel_launch(void* const* d_in, const int* in_sizes, int n_in,
                              void* d_out, int out_size)
{
    const float* x      = (const float*)d_in[0];
    const int*   mapped = (const int*)  d_in[1];
    const float* Wg     = (const float*)d_in[2];
    const float* bg     = (const float*)d_in[3];
    const float* Wi     = (const float*)d_in[4];
    const float* bi     = (const float*)d_in[5];
    const float* Wo     = (const float*)d_in[6];
    const float* bo     = (const float*)d_in[7];
    float* out = (float*)d_out;

    cudaFuncSetAttribute(up_gemm,   cudaFuncAttributeMaxDynamicSharedMemorySize, SMEM_SZ);
    cudaFuncSetAttribute(down_gemm, cudaFuncAttributeMaxDynamicSharedMemorySize, SMEM_SZ);

    route_kernel<<<1, 256>>>(mapped);
    prep_x_kernel<<<PADN, 256>>>(x);
    prep_wT_kernel<<<dim3(HID / 64, CDIM / 64, NEXP), 256>>>(Wg, Wi, Wo, 0);
    prep_wT_kernel<<<dim3(HID / 64, CDIM / 64, NEXP), 256>>>(Wg, Wi, Wo, 1);
    prep_wT_kernel<<<dim3(CDIM / 64, HID / 64, NEXP), 256>>>(Wg, Wi, Wo, 2);

    up_gemm<<<dim3(MTILES, HID / 64), 256, SMEM_SZ>>>(bg, bi);      // 40 x 48
    down_gemm<<<dim3(MTILES, CDIM / 128), 256, SMEM_SZ>>>(bo, out); // 40 x 6
}

// round 16
// speedup vs baseline: 1.1830x; 1.1830x over previous
#include <cuda_runtime.h>
#include <cuda_bf16.h>
#include <math.h>
#include <cstdint>

#define NTOK 4096
#define NEXP 8
#define CDIM 768
#define HID  3072
#define TM   128
#define PADN (NTOK + NEXP * TM)   // 5120
#define MTILES (PADN / TM)        // 40

#define APITCH 144                // 32 floats + 16B pad; A and B rows
#define SB_OFF 18432              // A tile 128*144
#define SSZ    36864              // stage: A 18432 + B 18432
#define SMEM_SZ 73728             // 2 stages (no epilogue staging needed now)

// ---------------- scratch ----------------
__device__ int g_perm[PADN];
__device__ int g_tile_expert[MTILES];
__device__ __align__(128) float g_xr[(size_t)PADN * CDIM];
__device__ __align__(128) float g_h[(size_t)PADN * HID];
// up weights transposed AND interleaved: row 2j = Wg[:,j], row 2j+1 = Wi[:,j]
__device__ __align__(128) float g_wupT[(size_t)NEXP * 2 * HID * CDIM];
__device__ __align__(128) float g_woT[(size_t)NEXP * CDIM * HID];   // [e][n][k]

// ---------------- helpers ----------------
static __device__ __forceinline__ uint32_t smem_u32(const void* p) {
    uint32_t a;
    asm("{ .reg .u64 t; cvta.to.shared.u64 t, %1; cvt.u32.u64 %0, t; }" : "=r"(a) : "l"(p));
    return a;
}
static __device__ __forceinline__ float tf32r(float x) {
    uint32_t u;
    asm("cvt.rna.tf32.f32 %0, %1;" : "=r"(u) : "f"(x));
    return __uint_as_float(u);
}
static __device__ __forceinline__ void ldsm4(uint32_t* r, uint32_t a) {
    asm volatile("ldmatrix.sync.aligned.m8n8.x4.shared.b16 {%0,%1,%2,%3}, [%4];"
        : "=r"(r[0]), "=r"(r[1]), "=r"(r[2]), "=r"(r[3]) : "r"(a));
}
static __device__ __forceinline__ void mma_tf32(float* c, const uint32_t* a,
                                                uint32_t b0, uint32_t b1) {
    asm volatile("mma.sync.aligned.m16n8k8.row.col.f32.tf32.tf32.f32 "
        "{%0,%1,%2,%3}, {%4,%5,%6,%7}, {%8,%9}, {%0,%1,%2,%3};"
        : "+f"(c[0]), "+f"(c[1]), "+f"(c[2]), "+f"(c[3])
        : "r"(a[0]), "r"(a[1]), "r"(a[2]), "r"(a[3]), "r"(b0), "r"(b1));
}

// ---------------------------------------------------------------------------
// route
// ---------------------------------------------------------------------------
__global__ void route_kernel(const int* __restrict__ mapped) {
    __shared__ int cnt[NEXP];
    __shared__ int off[NEXP];
    __shared__ int fill[NEXP];
    int tid = threadIdx.x;
    if (tid < NEXP) { cnt[tid] = 0; fill[tid] = 0; }
    __syncthreads();
    for (int i = tid; i < NTOK; i += blockDim.x) atomicAdd(&cnt[mapped[i]], 1);
    __syncthreads();
    if (tid == 0) {
        int o = 0;
        for (int e = 0; e < NEXP; e++) {
            off[e] = o;
            int tiles = (cnt[e] + TM - 1) / TM;
            for (int t = 0; t < tiles; t++) g_tile_expert[o / TM + t] = e;
            o += tiles * TM;
        }
        for (int t = o / TM; t < MTILES; t++) g_tile_expert[t] = -1;
    }
    __syncthreads();
    for (int i = tid; i < PADN; i += blockDim.x) g_perm[i] = -1;
    __syncthreads();
    for (int i = tid; i < NTOK; i += blockDim.x) {
        int e = mapped[i];
        g_perm[off[e] + atomicAdd(&fill[e], 1)] = i;
    }
}

// ---------------------------------------------------------------------------
// prep_x: gather-permute x rows + round to tf32 (pad rows -> 0)
// ---------------------------------------------------------------------------
__global__ __launch_bounds__(256) void prep_x_kernel(const float* __restrict__ x) {
    int row = blockIdx.x, tid = threadIdx.x;
    int prow = g_perm[row];
    const float* xr = (prow >= 0) ? x + (size_t)prow * CDIM : nullptr;
    #pragma unroll
    for (int j = 0; j < 3; j++) {
        int i = tid + 256 * j;
        float v = xr ? xr[i] : 0.0f;
        g_xr[(size_t)row * CDIM + i] = tf32r(v);
    }
}

// ---------------------------------------------------------------------------
// prep_wup: transpose+interleave Wg/Wi [K][N] -> g_wupT rows 2n / 2n+1.
// blockIdx.z = e*2 + which. dst selected device-side (host can't pass
// __device__ symbols -- the R6/R13 bug class).
// ---------------------------------------------------------------------------
__global__ __launch_bounds__(256) void prep_wup_kernel(
    const float* __restrict__ Wg, const float* __restrict__ Wi)
{
    __shared__ float ts[64][65];
    int which = blockIdx.z & 1;
    int e = blockIdx.z >> 1;
    const float* src = which ? Wi : Wg;
    int n0 = blockIdx.x * 64, k0 = blockIdx.y * 64;
    const float* se = src + (size_t)e * CDIM * HID;
    float* de = g_wupT + (size_t)e * 2 * HID * CDIM;
    int tid = threadIdx.x;
    int r = tid >> 4, c4 = tid & 15;
    #pragma unroll
    for (int i = 0; i < 4; i++) {
        int row = r + 16 * i;
        float4 v = *(const float4*)(se + (size_t)(k0 + row) * HID + n0 + c4 * 4);
        ts[row][c4 * 4 + 0] = tf32r(v.x);
        ts[row][c4 * 4 + 1] = tf32r(v.y);
        ts[row][c4 * 4 + 2] = tf32r(v.z);
        ts[row][c4 * 4 + 3] = tf32r(v.w);
    }
    __syncthreads();
    #pragma unroll
    for (int i = 0; i < 4; i++) {
        int n = r + 16 * i;
        float4 o;
        o.x = ts[c4 * 4 + 0][n];
        o.y = ts[c4 * 4 + 1][n];
        o.z = ts[c4 * 4 + 2][n];
        o.w = ts[c4 * 4 + 3][n];
        *(float4*)(de + (size_t)(2 * (n0 + n) + which) * CDIM + k0 + c4 * 4) = o;
    }
}

// ---------------------------------------------------------------------------
// prep_wo: transpose Wo [HID][CDIM] -> g_woT [CDIM][HID] with tf32 rounding
// ---------------------------------------------------------------------------
__global__ __launch_bounds__(256) void prep_wo_kernel(const float* __restrict__ Wo) {
    __shared__ float ts[64][65];
    int e = blockIdx.z;
    int n0 = blockIdx.x * 64, k0 = blockIdx.y * 64;
    const float* se = Wo + (size_t)e * HID * CDIM;
    float* de = g_woT + (size_t)e * CDIM * HID;
    int tid = threadIdx.x;
    int r = tid >> 4, c4 = tid & 15;
    #pragma unroll
    for (int i = 0; i < 4; i++) {
        int row = r + 16 * i;
        float4 v = *(const float4*)(se + (size_t)(k0 + row) * CDIM + n0 + c4 * 4);
        ts[row][c4 * 4 + 0] = tf32r(v.x);
        ts[row][c4 * 4 + 1] = tf32r(v.y);
        ts[row][c4 * 4 + 2] = tf32r(v.z);
        ts[row][c4 * 4 + 3] = tf32r(v.w);
    }
    __syncthreads();
    #pragma unroll
    for (int i = 0; i < 4; i++) {
        int n = r + 16 * i;
        float4 o;
        o.x = ts[c4 * 4 + 0][n];
        o.y = ts[c4 * 4 + 1][n];
        o.z = ts[c4 * 4 + 2][n];
        o.w = ts[c4 * 4 + 3][n];
        *(float4*)(de + (size_t)(n0 + n) * HID + k0 + c4 * 4) = o;
    }
}

// ---------------------------------------------------------------------------
// up GEMM: [128 tok] x interleaved [G|I] 64 h-cols, K=768, double-buffered.
// B rows interleaved -> (c0,c1)=(G,I) same thread; register-only epilogue.
// ---------------------------------------------------------------------------
__global__ __launch_bounds__(256, 2) void up_gemm(
    const float* __restrict__ bg, const float* __restrict__ bi)
{
    extern __shared__ char smem[];
    int mtile = blockIdx.x;
    int e = g_tile_expert[mtile];
    if (e < 0) return;
    int gn0 = blockIdx.y * 64;   // h-column offset
    int tid = threadIdx.x, lane = tid & 31, wid = tid >> 5;
    int wm = wid >> 2, wn = wid & 3;
    uint32_t sb = smem_u32(smem);

    const float* pA = g_xr + (size_t)(mtile * TM + (tid >> 1)) * CDIM + (tid & 1) * 16;
    int aoff = (tid >> 1) * APITCH + (tid & 1) * 64;
    int brow = tid >> 1;   // interleaved row 0..127 of this block
    const float* pB = g_wupT + ((size_t)e * 2 * HID + 2 * gn0 + brow) * CDIM + (tid & 1) * 16;
    int boff = SB_OFF + brow * APITCH + (tid & 1) * 64;

    float4 ra[4], rb[4];
    #pragma unroll
    for (int i = 0; i < 4; i++) { ra[i] = ((const float4*)pA)[i]; rb[i] = ((const float4*)pB)[i]; }
    #pragma unroll
    for (int i = 0; i < 4; i++) {
        *(float4*)(smem + aoff + i * 16) = ra[i];
        *(float4*)(smem + boff + i * 16) = rb[i];
    }
    __syncthreads();

    float acc[4][4][4] = {};
    int l7 = lane & 7, lb8 = ((lane >> 3) & 1) * 8, lh = lane >> 4;
    int a_lane = (l7 + lb8) * APITCH + lh * 16;
    int bgrp = lane >> 2, bk = lane & 3;
    int b_base = SB_OFF + (wn * 32 + bgrp) * APITCH + bk * 4;

    for (int s = 0; s < 24; s++) {
        int cso = (s & 1) * SSZ;
        if (s < 23) {
            const float4* nA = (const float4*)(pA + (s + 1) * 32);
            const float4* nB = (const float4*)(pB + (s + 1) * 32);
            #pragma unroll
            for (int i = 0; i < 4; i++) { ra[i] = nA[i]; rb[i] = nB[i]; }
        }
        #pragma unroll
        for (int c = 0; c < 4; c++) {
            uint32_t a[4][4];
            #pragma unroll
            for (int mi = 0; mi < 4; mi++)
                ldsm4(a[mi], sb + cso + (wm * 64 + mi * 16) * APITCH + a_lane + c * 32);
            uint32_t b0[4], b1[4];
            int kb = cso + b_base + c * 32;
            #pragma unroll
            for (int nj = 0; nj < 4; nj++) {
                b0[nj] = *(const uint32_t*)(smem + kb + nj * 8 * APITCH);
                b1[nj] = *(const uint32_t*)(smem + kb + nj * 8 * APITCH + 16);
            }
            #pragma unroll
            for (int mi = 0; mi < 4; mi++)
                #pragma unroll
                for (int nj = 0; nj < 4; nj++)
                    mma_tf32(acc[mi][nj], a[mi], b0[nj], b1[nj]);
        }
        if (s < 23) {
            int nso = ((s + 1) & 1) * SSZ;
            #pragma unroll
            for (int i = 0; i < 4; i++) {
                *(float4*)(smem + nso + aoff + i * 16) = ra[i];
                *(float4*)(smem + nso + boff + i * 16) = rb[i];
            }
        }
        __syncthreads();
    }

    // register epilogue: (c0,c1)=(G,I) row r0; (c2,c3)=(G,I) row r0+8
    int g = lane >> 2, tq = lane & 3;
    const float* bgp = bg + (size_t)e * HID + gn0;
    const float* bip = bi + (size_t)e * HID + gn0;
    #pragma unroll
    for (int mi = 0; mi < 4; mi++) {
        int r0 = wm * 64 + mi * 16 + g;
        float* h0 = g_h + (size_t)(mtile * TM + r0) * HID + gn0;
        float* h1 = g_h + (size_t)(mtile * TM + r0 + 8) * HID + gn0;
        #pragma unroll
        for (int nj = 0; nj < 4; nj++) {
            int colh = wn * 16 + nj * 4 + tq;
            float bgv = bgp[colh], biv = bip[colh];
            float gv0 = acc[mi][nj][0] + bgv;
            float iv0 = acc[mi][nj][1] + biv;
            h0[colh] = tf32r((gv0 / (1.0f + __expf(-gv0))) * iv0);
            float gv1 = acc[mi][nj][2] + bgv;
            float iv1 = acc[mi][nj][3] + biv;
            h1[colh] = tf32r((gv1 / (1.0f + __expf(-gv1))) * iv1);
        }
    }
}

// ---------------------------------------------------------------------------
// down GEMM: y = h @ Wo + bo, K=3072, BN=128, double-buffered, scatter.
// (verbatim R14)
// ---------------------------------------------------------------------------
__global__ __launch_bounds__(256, 2) void down_gemm(
    const float* __restrict__ bo, float* __restrict__ out)
{
    extern __shared__ char smem[];
    int mtile = blockIdx.x;
    int e = g_tile_expert[mtile];
    if (e < 0) return;
    int gn0 = blockIdx.y * 128;
    int tid = threadIdx.x, lane = tid & 31, wid = tid >> 5;
    int wm = wid >> 2, wn = wid & 3;
    uint32_t sb = smem_u32(smem);

    const float* pA = g_h + (size_t)(mtile * TM + (tid >> 1)) * HID + (tid & 1) * 16;
    int aoff = (tid >> 1) * APITCH + (tid & 1) * 64;
    int brow = tid >> 1;
    const float* pB = g_woT + ((size_t)e * CDIM + gn0 + brow) * HID + (tid & 1) * 16;
    int boff = SB_OFF + brow * APITCH + (tid & 1) * 64;

    float4 ra[4], rb[4];
    #pragma unroll
    for (int i = 0; i < 4; i++) { ra[i] = ((const float4*)pA)[i]; rb[i] = ((const float4*)pB)[i]; }
    #pragma unroll
    for (int i = 0; i < 4; i++) {
        *(float4*)(smem + aoff + i * 16) = ra[i];
        *(float4*)(smem + boff + i * 16) = rb[i];
    }
    __syncthreads();

    float acc[4][4][4] = {};
    int l7 = lane & 7, lb8 = ((lane >> 3) & 1) * 8, lh = lane >> 4;
    int a_lane = (l7 + lb8) * APITCH + lh * 16;
    int bgrp = lane >> 2, bk = lane & 3;
    int b_base = SB_OFF + (wn * 32 + bgrp) * APITCH + bk * 4;

    for (int s = 0; s < 96; s++) {
        int cso = (s & 1) * SSZ;
        if (s < 95) {
            const float4* nA = (const float4*)(pA + (s + 1) * 32);
            const float4* nB = (const float4*)(pB + (s + 1) * 32);
            #pragma unroll
            for (int i = 0; i < 4; i++) { ra[i] = nA[i]; rb[i] = nB[i]; }
        }
        #pragma unroll
        for (int c = 0; c < 4; c++) {
            uint32_t a[4][4];
            #pragma unroll
            for (int mi = 0; mi < 4; mi++)
                ldsm4(a[mi], sb + cso + (wm * 64 + mi * 16) * APITCH + a_lane + c * 32);
            uint32_t b0[4], b1[4];
            int kb = cso + b_base + c * 32;
            #pragma unroll
            for (int nj = 0; nj < 4; nj++) {
                b0[nj] = *(const uint32_t*)(smem + kb + nj * 8 * APITCH);
                b1[nj] = *(const uint32_t*)(smem + kb + nj * 8 * APITCH + 16);
            }
            #pragma unroll
            for (int mi = 0; mi < 4; mi++)
                #pragma unroll
                for (int nj = 0; nj < 4; nj++)
                    mma_tf32(acc[mi][nj], a[mi], b0[nj], b1[nj]);
        }
        if (s < 95) {
            int nso = ((s + 1) & 1) * SSZ;
            #pragma unroll
            for (int i = 0; i < 4; i++) {
                *(float4*)(smem + nso + aoff + i * 16) = ra[i];
                *(float4*)(smem + nso + boff + i * 16) = rb[i];
            }
        }
        __syncthreads();
    }

    int g = lane >> 2, tq = lane & 3;
    const float* bop = bo + (size_t)e * CDIM;
    #pragma unroll
    for (int mi = 0; mi < 4; mi++) {
        int r0 = wm * 64 + mi * 16 + g;
        int p0 = g_perm[mtile * TM + r0];
        int p1 = g_perm[mtile * TM + r0 + 8];
        #pragma unroll
        for (int nj = 0; nj < 4; nj++) {
            int col = gn0 + wn * 32 + nj * 8 + 2 * tq;
            float2 b = *(const float2*)(bop + col);
            if (p0 >= 0)
                *(float2*)&out[(size_t)p0 * CDIM + col] =
                    make_float2(acc[mi][nj][0] + b.x, acc[mi][nj][1] + b.y);
            if (p1 >= 0)
                *(float2*)&out[(size_t)p1 * CDIM + col] =
                    make_float2(acc[mi][nj][2] + b.x, acc[mi][nj][3] + b.y);
        }
    }
}

// ---------------------------------------------------------------------------
extern "C" void kernel_launch(void* const* d_in, const int* in_sizes, int n_in,
                              void* d_out, int out_size)
{
    const float* x      = (const float*)d_in[0];
    const int*   mapped = (const int*)  d_in[1];
    const float* Wg     = (const float*)d_in[2];
    const float* bg     = (const float*)d_in[3];
    const float* Wi     = (const float*)d_in[4];
    const float* bi     = (const float*)d_in[5];
    const float* Wo     = (const float*)d_in[6];
    const float* bo     = (const float*)d_in[7];
    float* out = (float*)d_out;

    cudaFuncSetAttribute(up_gemm,   cudaFuncAttributeMaxDynamicSharedMemorySize, SMEM_SZ);
    cudaFuncSetAttribute(down_gemm, cudaFuncAttributeMaxDynamicSharedMemorySize, SMEM_SZ);

    route_kernel<<<1, 256>>>(mapped);
    prep_x_kernel<<<PADN, 256>>>(x);
    prep_wup_kernel<<<dim3(HID / 64, CDIM / 64, NEXP * 2), 256>>>(Wg, Wi);
    prep_wo_kernel<<<dim3(CDIM / 64, HID / 64, NEXP), 256>>>(Wo);

    up_gemm<<<dim3(MTILES, HID / 64), 256, SMEM_SZ>>>(bg, bi);      // 40 x 48
    down_gemm<<<dim3(MTILES, CDIM / 128), 256, SMEM_SZ>>>(bo, out); // 40 x 6
}

// round 17
// speedup vs baseline: 1.3727x; 1.1603x over previous
#include <cuda_runtime.h>
#include <cuda_bf16.h>
#include <math.h>
#include <cstdint>

#define NTOK 4096
#define NEXP 8
#define CDIM 768
#define HID  3072
#define TM   128
#define PADN (NTOK + NEXP * TM)   // 5120
#define MTILES (PADN / TM)        // 40

#define APITCH 144                // 32 floats + 16B pad
#define SB_OFF 18432              // A tile 128*144
#define SSZ    55296              // stage: A 18432 + B 256*144
#define SMEM_SZ 110592            // 2 stages

// ---------------- scratch ----------------
__device__ int g_perm[PADN];
__device__ int g_tile_expert[MTILES];
__device__ __align__(128) float g_xr[(size_t)PADN * CDIM];
__device__ __align__(128) float g_h[(size_t)PADN * HID];
// up weights transposed AND interleaved: row 2j = Wg[:,j], row 2j+1 = Wi[:,j]
__device__ __align__(128) float g_wupT[(size_t)NEXP * 2 * HID * CDIM];
__device__ __align__(128) float g_woT[(size_t)NEXP * CDIM * HID];   // [e][n][k]

// ---------------- helpers ----------------
static __device__ __forceinline__ uint32_t smem_u32(const void* p) {
    uint32_t a;
    asm("{ .reg .u64 t; cvta.to.shared.u64 t, %1; cvt.u32.u64 %0, t; }" : "=r"(a) : "l"(p));
    return a;
}
static __device__ __forceinline__ float tf32r(float x) {
    uint32_t u;
    asm("cvt.rna.tf32.f32 %0, %1;" : "=r"(u) : "f"(x));
    return __uint_as_float(u);
}
static __device__ __forceinline__ void ldsm4(uint32_t* r, uint32_t a) {
    asm volatile("ldmatrix.sync.aligned.m8n8.x4.shared.b16 {%0,%1,%2,%3}, [%4];"
        : "=r"(r[0]), "=r"(r[1]), "=r"(r[2]), "=r"(r[3]) : "r"(a));
}
static __device__ __forceinline__ void mma_tf32(float* c, const uint32_t* a,
                                                uint32_t b0, uint32_t b1) {
    asm volatile("mma.sync.aligned.m16n8k8.row.col.f32.tf32.tf32.f32 "
        "{%0,%1,%2,%3}, {%4,%5,%6,%7}, {%8,%9}, {%0,%1,%2,%3};"
        : "+f"(c[0]), "+f"(c[1]), "+f"(c[2]), "+f"(c[3])
        : "r"(a[0]), "r"(a[1]), "r"(a[2]), "r"(a[3]), "r"(b0), "r"(b1));
}

// ---------------------------------------------------------------------------
// route
// ---------------------------------------------------------------------------
__global__ void route_kernel(const int* __restrict__ mapped) {
    __shared__ int cnt[NEXP];
    __shared__ int off[NEXP];
    __shared__ int fill[NEXP];
    int tid = threadIdx.x;
    if (tid < NEXP) { cnt[tid] = 0; fill[tid] = 0; }
    __syncthreads();
    for (int i = tid; i < NTOK; i += blockDim.x) atomicAdd(&cnt[mapped[i]], 1);
    __syncthreads();
    if (tid == 0) {
        int o = 0;
        for (int e = 0; e < NEXP; e++) {
            off[e] = o;
            int tiles = (cnt[e] + TM - 1) / TM;
            for (int t = 0; t < tiles; t++) g_tile_expert[o / TM + t] = e;
            o += tiles * TM;
        }
        for (int t = o / TM; t < MTILES; t++) g_tile_expert[t] = -1;
    }
    __syncthreads();
    for (int i = tid; i < PADN; i += blockDim.x) g_perm[i] = -1;
    __syncthreads();
    for (int i = tid; i < NTOK; i += blockDim.x) {
        int e = mapped[i];
        g_perm[off[e] + atomicAdd(&fill[e], 1)] = i;
    }
}

// ---------------------------------------------------------------------------
// prep_x: gather-permute x rows + round to tf32 (pad rows -> 0)
// ---------------------------------------------------------------------------
__global__ __launch_bounds__(256) void prep_x_kernel(const float* __restrict__ x) {
    int row = blockIdx.x, tid = threadIdx.x;
    int prow = g_perm[row];
    const float* xr = (prow >= 0) ? x + (size_t)prow * CDIM : nullptr;
    #pragma unroll
    for (int j = 0; j < 3; j++) {
        int i = tid + 256 * j;
        float v = xr ? xr[i] : 0.0f;
        g_xr[(size_t)row * CDIM + i] = tf32r(v);
    }
}

// ---------------------------------------------------------------------------
// prep_wup: transpose+interleave Wg/Wi [K][N] -> g_wupT rows 2n / 2n+1.
// dst device-side (host can't pass __device__ symbols).
// ---------------------------------------------------------------------------
__global__ __launch_bounds__(256) void prep_wup_kernel(
    const float* __restrict__ Wg, const float* __restrict__ Wi)
{
    __shared__ float ts[64][65];
    int which = blockIdx.z & 1;
    int e = blockIdx.z >> 1;
    const float* src = which ? Wi : Wg;
    int n0 = blockIdx.x * 64, k0 = blockIdx.y * 64;
    const float* se = src + (size_t)e * CDIM * HID;
    float* de = g_wupT + (size_t)e * 2 * HID * CDIM;
    int tid = threadIdx.x;
    int r = tid >> 4, c4 = tid & 15;
    #pragma unroll
    for (int i = 0; i < 4; i++) {
        int row = r + 16 * i;
        float4 v = *(const float4*)(se + (size_t)(k0 + row) * HID + n0 + c4 * 4);
        ts[row][c4 * 4 + 0] = tf32r(v.x);
        ts[row][c4 * 4 + 1] = tf32r(v.y);
        ts[row][c4 * 4 + 2] = tf32r(v.z);
        ts[row][c4 * 4 + 3] = tf32r(v.w);
    }
    __syncthreads();
    #pragma unroll
    for (int i = 0; i < 4; i++) {
        int n = r + 16 * i;
        float4 o;
        o.x = ts[c4 * 4 + 0][n];
        o.y = ts[c4 * 4 + 1][n];
        o.z = ts[c4 * 4 + 2][n];
        o.w = ts[c4 * 4 + 3][n];
        *(float4*)(de + (size_t)(2 * (n0 + n) + which) * CDIM + k0 + c4 * 4) = o;
    }
}

// ---------------------------------------------------------------------------
// prep_wo: transpose Wo [HID][CDIM] -> g_woT [CDIM][HID] with tf32 rounding
// ---------------------------------------------------------------------------
__global__ __launch_bounds__(256) void prep_wo_kernel(const float* __restrict__ Wo) {
    __shared__ float ts[64][65];
    int e = blockIdx.z;
    int n0 = blockIdx.x * 64, k0 = blockIdx.y * 64;
    const float* se = Wo + (size_t)e * HID * CDIM;
    float* de = g_woT + (size_t)e * CDIM * HID;
    int tid = threadIdx.x;
    int r = tid >> 4, c4 = tid & 15;
    #pragma unroll
    for (int i = 0; i < 4; i++) {
        int row = r + 16 * i;
        float4 v = *(const float4*)(se + (size_t)(k0 + row) * CDIM + n0 + c4 * 4);
        ts[row][c4 * 4 + 0] = tf32r(v.x);
        ts[row][c4 * 4 + 1] = tf32r(v.y);
        ts[row][c4 * 4 + 2] = tf32r(v.z);
        ts[row][c4 * 4 + 3] = tf32r(v.w);
    }
    __syncthreads();
    #pragma unroll
    for (int i = 0; i < 4; i++) {
        int n = r + 16 * i;
        float4 o;
        o.x = ts[c4 * 4 + 0][n];
        o.y = ts[c4 * 4 + 1][n];
        o.z = ts[c4 * 4 + 2][n];
        o.w = ts[c4 * 4 + 3][n];
        *(float4*)(de + (size_t)(n0 + n) * HID + k0 + c4 * 4) = o;
    }
}

// ---------------------------------------------------------------------------
// up GEMM: CTA 128 tok x 256 interleaved rows (128 h-cols), K=768.
// 512 threads, 16 warps (2m x 8n), warp tile 64x32 (unchanged code).
// ---------------------------------------------------------------------------
__global__ __launch_bounds__(512, 1) void up_gemm(
    const float* __restrict__ bg, const float* __restrict__ bi)
{
    extern __shared__ char smem[];
    int mtile = blockIdx.x;
    int e = g_tile_expert[mtile];
    if (e < 0) return;
    int gn0 = blockIdx.y * 128;   // h-column offset (256 interleaved rows)
    int tid = threadIdx.x, lane = tid & 31, wid = tid >> 5;
    int wm = wid >> 3, wn = wid & 7;
    uint32_t sb = smem_u32(smem);

    // A loader: 8 floats/thread (128 rows x 4 quarters)
    const float* pA = g_xr + (size_t)(mtile * TM + (tid >> 2)) * CDIM + (tid & 3) * 8;
    int aoff = (tid >> 2) * APITCH + (tid & 3) * 32;
    // B loader: 16 floats/thread (256 rows x 2 halves)
    int brow = tid >> 1;
    const float* pB = g_wupT + ((size_t)e * 2 * HID + 2 * gn0 + brow) * CDIM + (tid & 1) * 16;
    int boff = SB_OFF + brow * APITCH + (tid & 1) * 64;

    float4 ra[2], rb[4];
    #pragma unroll
    for (int i = 0; i < 2; i++) ra[i] = ((const float4*)pA)[i];
    #pragma unroll
    for (int i = 0; i < 4; i++) rb[i] = ((const float4*)pB)[i];
    #pragma unroll
    for (int i = 0; i < 2; i++) *(float4*)(smem + aoff + i * 16) = ra[i];
    #pragma unroll
    for (int i = 0; i < 4; i++) *(float4*)(smem + boff + i * 16) = rb[i];
    __syncthreads();

    float acc[4][4][4] = {};
    int l7 = lane & 7, lb8 = ((lane >> 3) & 1) * 8, lh = lane >> 4;
    int a_lane = (l7 + lb8) * APITCH + lh * 16;
    int bgrp = lane >> 2, bk = lane & 3;
    int b_base = SB_OFF + (wn * 32 + bgrp) * APITCH + bk * 4;

    for (int s = 0; s < 24; s++) {
        int cso = (s & 1) * SSZ;
        if (s < 23) {
            const float4* nA = (const float4*)(pA + (s + 1) * 32);
            const float4* nB = (const float4*)(pB + (s + 1) * 32);
            #pragma unroll
            for (int i = 0; i < 2; i++) ra[i] = nA[i];
            #pragma unroll
            for (int i = 0; i < 4; i++) rb[i] = nB[i];
        }
        #pragma unroll
        for (int c = 0; c < 4; c++) {
            uint32_t a[4][4];
            #pragma unroll
            for (int mi = 0; mi < 4; mi++)
                ldsm4(a[mi], sb + cso + (wm * 64 + mi * 16) * APITCH + a_lane + c * 32);
            uint32_t b0[4], b1[4];
            int kb = cso + b_base + c * 32;
            #pragma unroll
            for (int nj = 0; nj < 4; nj++) {
                b0[nj] = *(const uint32_t*)(smem + kb + nj * 8 * APITCH);
                b1[nj] = *(const uint32_t*)(smem + kb + nj * 8 * APITCH + 16);
            }
            #pragma unroll
            for (int mi = 0; mi < 4; mi++)
                #pragma unroll
                for (int nj = 0; nj < 4; nj++)
                    mma_tf32(acc[mi][nj], a[mi], b0[nj], b1[nj]);
        }
        if (s < 23) {
            int nso = ((s + 1) & 1) * SSZ;
            #pragma unroll
            for (int i = 0; i < 2; i++) *(float4*)(smem + nso + aoff + i * 16) = ra[i];
            #pragma unroll
            for (int i = 0; i < 4; i++) *(float4*)(smem + nso + boff + i * 16) = rb[i];
        }
        __syncthreads();
    }

    // register epilogue: (c0,c1)=(G,I) row r0; (c2,c3)=(G,I) row r0+8
    int g = lane >> 2, tq = lane & 3;
    const float* bgp = bg + (size_t)e * HID + gn0;
    const float* bip = bi + (size_t)e * HID + gn0;
    #pragma unroll
    for (int mi = 0; mi < 4; mi++) {
        int r0 = wm * 64 + mi * 16 + g;
        float* h0 = g_h + (size_t)(mtile * TM + r0) * HID + gn0;
        float* h1 = g_h + (size_t)(mtile * TM + r0 + 8) * HID + gn0;
        #pragma unroll
        for (int nj = 0; nj < 4; nj++) {
            int colh = wn * 16 + nj * 4 + tq;
            float bgv = bgp[colh], biv = bip[colh];
            float gv0 = acc[mi][nj][0] + bgv;
            float iv0 = acc[mi][nj][1] + biv;
            h0[colh] = tf32r((gv0 / (1.0f + __expf(-gv0))) * iv0);
            float gv1 = acc[mi][nj][2] + bgv;
            float iv1 = acc[mi][nj][3] + biv;
            h1[colh] = tf32r((gv1 / (1.0f + __expf(-gv1))) * iv1);
        }
    }
}

// ---------------------------------------------------------------------------
// down GEMM: y = h @ Wo + bo, CTA 128 x 256, K=3072, scatter via perm.
// 512 threads, 16 warps (2m x 8n).
// ---------------------------------------------------------------------------
__global__ __launch_bounds__(512, 1) void down_gemm(
    const float* __restrict__ bo, float* __restrict__ out)
{
    extern __shared__ char smem[];
    int mtile = blockIdx.x;
    int e = g_tile_expert[mtile];
    if (e < 0) return;
    int gn0 = blockIdx.y * 256;
    int tid = threadIdx.x, lane = tid & 31, wid = tid >> 5;
    int wm = wid >> 3, wn = wid & 7;
    uint32_t sb = smem_u32(smem);

    const float* pA = g_h + (size_t)(mtile * TM + (tid >> 2)) * HID + (tid & 3) * 8;
    int aoff = (tid >> 2) * APITCH + (tid & 3) * 32;
    int brow = tid >> 1;
    const float* pB = g_woT + ((size_t)e * CDIM + gn0 + brow) * HID + (tid & 1) * 16;
    int boff = SB_OFF + brow * APITCH + (tid & 1) * 64;

    float4 ra[2], rb[4];
    #pragma unroll
    for (int i = 0; i < 2; i++) ra[i] = ((const float4*)pA)[i];
    #pragma unroll
    for (int i = 0; i < 4; i++) rb[i] = ((const float4*)pB)[i];
    #pragma unroll
    for (int i = 0; i < 2; i++) *(float4*)(smem + aoff + i * 16) = ra[i];
    #pragma unroll
    for (int i = 0; i < 4; i++) *(float4*)(smem + boff + i * 16) = rb[i];
    __syncthreads();

    float acc[4][4][4] = {};
    int l7 = lane & 7, lb8 = ((lane >> 3) & 1) * 8, lh = lane >> 4;
    int a_lane = (l7 + lb8) * APITCH + lh * 16;
    int bgrp = lane >> 2, bk = lane & 3;
    int b_base = SB_OFF + (wn * 32 + bgrp) * APITCH + bk * 4;

    for (int s = 0; s < 96; s++) {
        int cso = (s & 1) * SSZ;
        if (s < 95) {
            const float4* nA = (const float4*)(pA + (s + 1) * 32);
            const float4* nB = (const float4*)(pB + (s + 1) * 32);
            #pragma unroll
            for (int i = 0; i < 2; i++) ra[i] = nA[i];
            #pragma unroll
            for (int i = 0; i < 4; i++) rb[i] = nB[i];
        }
        #pragma unroll
        for (int c = 0; c < 4; c++) {
            uint32_t a[4][4];
            #pragma unroll
            for (int mi = 0; mi < 4; mi++)
                ldsm4(a[mi], sb + cso + (wm * 64 + mi * 16) * APITCH + a_lane + c * 32);
            uint32_t b0[4], b1[4];
            int kb = cso + b_base + c * 32;
            #pragma unroll
            for (int nj = 0; nj < 4; nj++) {
                b0[nj] = *(const uint32_t*)(smem + kb + nj * 8 * APITCH);
                b1[nj] = *(const uint32_t*)(smem + kb + nj * 8 * APITCH + 16);
            }
            #pragma unroll
            for (int mi = 0; mi < 4; mi++)
                #pragma unroll
                for (int nj = 0; nj < 4; nj++)
                    mma_tf32(acc[mi][nj], a[mi], b0[nj], b1[nj]);
        }
        if (s < 95) {
            int nso = ((s + 1) & 1) * SSZ;
            #pragma unroll
            for (int i = 0; i < 2; i++) *(float4*)(smem + nso + aoff + i * 16) = ra[i];
            #pragma unroll
            for (int i = 0; i < 4; i++) *(float4*)(smem + nso + boff + i * 16) = rb[i];
        }
        __syncthreads();
    }

    int g = lane >> 2, tq = lane & 3;
    const float* bop = bo + (size_t)e * CDIM;
    #pragma unroll
    for (int mi = 0; mi < 4; mi++) {
        int r0 = wm * 64 + mi * 16 + g;
        int p0 = g_perm[mtile * TM + r0];
        int p1 = g_perm[mtile * TM + r0 + 8];
        #pragma unroll
        for (int nj = 0; nj < 4; nj++) {
            int col = gn0 + wn * 32 + nj * 8 + 2 * tq;
            float2 b = *(const float2*)(bop + col);
            if (p0 >= 0)
                *(float2*)&out[(size_t)p0 * CDIM + col] =
                    make_float2(acc[mi][nj][0] + b.x, acc[mi][nj][1] + b.y);
            if (p1 >= 0)
                *(float2*)&out[(size_t)p1 * CDIM + col] =
                    make_float2(acc[mi][nj][2] + b.x, acc[mi][nj][3] + b.y);
        }
    }
}

// ---------------------------------------------------------------------------
extern "C" void kernel_launch(void* const* d_in, const int* in_sizes, int n_in,
                              void* d_out, int out_size)
{
    const float* x      = (const float*)d_in[0];
    const int*   mapped = (const int*)  d_in[1];
    const float* Wg     = (const float*)d_in[2];
    const float* bg     = (const float*)d_in[3];
    const float* Wi     = (const float*)d_in[4];
    const float* bi     = (const float*)d_in[5];
    const float* Wo     = (const float*)d_in[6];
    const float* bo     = (const float*)d_in[7];
    float* out = (float*)d_out;

    cudaFuncSetAttribute(up_gemm,   cudaFuncAttributeMaxDynamicSharedMemorySize, SMEM_SZ);
    cudaFuncSetAttribute(down_gemm, cudaFuncAttributeMaxDynamicSharedMemorySize, SMEM_SZ);

    route_kernel<<<1, 256>>>(mapped);
    prep_x_kernel<<<PADN, 256>>>(x);
    prep_wup_kernel<<<dim3(HID / 64, CDIM / 64, NEXP * 2), 256>>>(Wg, Wi);
    prep_wo_kernel<<<dim3(CDIM / 64, HID / 64, NEXP), 256>>>(Wo);

    up_gemm<<<dim3(MTILES, HID / 128), 512, SMEM_SZ>>>(bg, bi);     // 40 x 24
    down_gemm<<<dim3(MTILES, CDIM / 256), 512, SMEM_SZ>>>(bo, out); // 40 x 3
}